// round 17
// baseline (speedup 1.0000x reference)
#include <cuda_runtime.h>
#include <cuda_fp16.h>
#include <cstdint>
#include <cstddef>

// ---------------------------------------------------------------------------
// Problem constants
// ---------------------------------------------------------------------------
#define BB 32
#define TT 2048
#define II 512
#define HH 512
#define MM (BB * TT)                 // 65536 GEMM rows
#define BH (BB * HH)                 // 16384
#define GSZ ((size_t)TT * BH)        // elems per gate plane

// Scratch (device globals; no runtime allocation allowed)
// g_pre layout: [t][b*H + h][4 gates]  (gate-interleaved, 512 MB)
__device__ float   g_pre[4ull * GSZ];
__device__ __half  g_x16[(size_t)MM * II];      // 64 MB, single fp16 plane
// W transposed + gate-interleaved fp16: row n' = h*4 + g, col k. [2048][512]
__device__ __half  g_wth[4ull * HH * II];

// ---------------------------------------------------------------------------
// Helpers (base-ISA only: cp.async / ldmatrix / mma.sync all work at sm_103)
// ---------------------------------------------------------------------------
__device__ __forceinline__ uint32_t smem_u32(const void* p) {
    uint32_t a;
    asm("{ .reg .u64 t; cvta.to.shared.u64 t, %1; cvt.u32.u64 %0, t; }"
        : "=r"(a) : "l"(p));
    return a;
}

#define SWZ128(off) ((off) ^ (((off) >> 3) & 0x70))

__device__ __forceinline__ void cp_async16(uint32_t saddr, const void* gaddr) {
    asm volatile("cp.async.cg.shared.global [%0], [%1], 16;"
                 :: "r"(saddr), "l"(gaddr));
}
#define CP_COMMIT() asm volatile("cp.async.commit_group;" ::: "memory")
#define CP_WAIT(n)  asm volatile("cp.async.wait_group %0;" :: "n"(n) : "memory")

__device__ __forceinline__ void ldmatrix_x4(uint32_t& r0, uint32_t& r1,
                                            uint32_t& r2, uint32_t& r3,
                                            uint32_t addr) {
    asm volatile("ldmatrix.sync.aligned.m8n8.x4.shared.b16 {%0,%1,%2,%3}, [%4];"
                 : "=r"(r0), "=r"(r1), "=r"(r2), "=r"(r3) : "r"(addr));
}
__device__ __forceinline__ void ldmatrix_x2(uint32_t& r0, uint32_t& r1,
                                            uint32_t addr) {
    asm volatile("ldmatrix.sync.aligned.m8n8.x2.shared.b16 {%0,%1}, [%2];"
                 : "=r"(r0), "=r"(r1) : "r"(addr));
}

__device__ __forceinline__ void mma_f16(float* c, const uint32_t* a,
                                        const uint32_t* b) {
    asm volatile(
        "mma.sync.aligned.m16n8k16.row.col.f32.f16.f16.f32 "
        "{%0,%1,%2,%3}, {%4,%5,%6,%7}, {%8,%9}, {%0,%1,%2,%3};"
        : "+f"(c[0]), "+f"(c[1]), "+f"(c[2]), "+f"(c[3])
        : "r"(a[0]), "r"(a[1]), "r"(a[2]), "r"(a[3]), "r"(b[0]), "r"(b[1]));
}

// ---------------------------------------------------------------------------
// Conversion kernels
// ---------------------------------------------------------------------------
__global__ __launch_bounds__(256) void convert_x_kernel(const float* __restrict__ x) {
    size_t i = ((size_t)blockIdx.x * 256 + threadIdx.x) * 4;
    float4 v = *(const float4*)(x + i);
    __half2* p = (__half2*)(g_x16 + i);
    p[0] = __half2(__float2half(v.x), __float2half(v.y));
    p[1] = __half2(__float2half(v.z), __float2half(v.w));
}

// W fp16, row n' = h*4 + g (gate-interleaved N), col k.
__global__ __launch_bounds__(256) void convert_w_kernel(
    const float* __restrict__ Wf, const float* __restrict__ Wi,
    const float* __restrict__ Wo, const float* __restrict__ Wc)
{
    int idx = blockIdx.x * 256 + threadIdx.x;       // [n'][k], 0 .. 4*512*512-1
    int np = idx >> 9;                              // 0..2047
    int k  = idx & 511;
    int h  = np >> 2;
    int g  = np & 3;
    const float* W = (g == 0) ? Wf : (g == 1) ? Wi : (g == 2) ? Wo : Wc;
    g_wth[idx] = __float2half(W[k * HH + h]);       // transpose: [k][h] -> [n'][k]
}

// ---------------------------------------------------------------------------
// mma.sync GEMM: M=65536, N=2048 (gate-interleaved), K=512.
// CTA: 128x128, BK=64, 8 warps (2x4), warp tile 64x32, fp32 reg accum.
// D = x16 * W16   (single fp16 term; fp32 accumulate)
// smem per stage: A(16K) B(16K) = 32KB; 2 stages = 64KB.
// grid = (16 n-tiles, 512 m-tiles)
// ---------------------------------------------------------------------------
#define BKC     64
#define NKCH    (II / BKC)           // 8 chunks
#define TILE_B  16384                // bytes per operand tile (128 x 128B)
#define STAGE_B (2 * TILE_B)         // 32KB
#define A_OFF   0
#define B_OFF   TILE_B

__global__ __launch_bounds__(256, 1) void gemm_mma_kernel() {
    extern __shared__ char smem[];
    const uint32_t sb = smem_u32(smem);
    const int tid  = threadIdx.x;
    const int lane = tid & 31;
    const int warp = tid >> 5;
    const int wm = warp >> 2;           // 0..1 -> M offset wm*64
    const int wn = warp & 3;            // 0..3 -> N offset wn*32

    const int nt = blockIdx.x;          // 0..15
    const int my = blockIdx.y;          // 0..511

    const __half* __restrict__ Ag = g_x16 + (size_t)my * 128 * II;
    const __half* __restrict__ Bg = g_wth + (size_t)nt * 128 * II;

    auto load_chunk = [&](int c, int s) {
        const uint32_t stg = sb + (uint32_t)s * STAGE_B;
        const int ko = c * BKC;
        #pragma unroll
        for (int i = 0; i < 4; i++) {
            const int u   = tid + i * 256;          // 0..1023
            const int row = u >> 3;
            const int un  = u & 7;
            const uint32_t so = SWZ128((uint32_t)(row * 128 + un * 16));
            const size_t  go = (size_t)row * II + ko + un * 8;
            cp_async16(stg + A_OFF + so, Ag + go);
            cp_async16(stg + B_OFF + so, Bg + go);
        }
        CP_COMMIT();
    };

    float acc[4][4][4];
    #pragma unroll
    for (int mi = 0; mi < 4; mi++)
        #pragma unroll
        for (int ni = 0; ni < 4; ni++)
            #pragma unroll
            for (int r = 0; r < 4; r++) acc[mi][ni][r] = 0.0f;

    const int arow = (lane & 15);                   // fragment row
    const int akseg = (lane >> 4) << 4;             // 0 or 16 bytes
    const int brow = (lane & 7);
    const int bkseg = ((lane >> 3) & 1) << 4;

    load_chunk(0, 0);

    for (int c = 0; c < NKCH; c++) {
        const int s = c & 1;
        if (c + 1 < NKCH) { load_chunk(c + 1, (c + 1) & 1); CP_WAIT(1); }
        else              { CP_WAIT(0); }
        __syncthreads();

        const uint32_t stg = sb + (uint32_t)s * STAGE_B;
        #pragma unroll
        for (int kk = 0; kk < 4; kk++) {
            const int kb = kk * 32;                 // byte offset of 16-k group
            uint32_t a[4][4], b[4][2];
            #pragma unroll
            for (int mi = 0; mi < 4; mi++) {
                const int r = wm * 64 + mi * 16 + arow;
                const uint32_t off = SWZ128((uint32_t)(r * 128 + kb + akseg));
                ldmatrix_x4(a[mi][0], a[mi][1], a[mi][2], a[mi][3],
                            stg + A_OFF + off);
            }
            #pragma unroll
            for (int ni = 0; ni < 4; ni++) {
                const int r = wn * 32 + ni * 8 + brow;
                const uint32_t off = SWZ128((uint32_t)(r * 128 + kb + bkseg));
                ldmatrix_x2(b[ni][0], b[ni][1], stg + B_OFF + off);
            }
            #pragma unroll
            for (int mi = 0; mi < 4; mi++)
                #pragma unroll
                for (int ni = 0; ni < 4; ni++)
                    mma_f16(acc[mi][ni], a[mi], b[ni]);
        }
        __syncthreads();
    }

    // ---- epilogue: direct stores into gate-interleaved time-major layout.
    // m = my*128 + r -> b_ = my>>4, t = (my&15)*128 + r
    // n (global, gate-interleaved) = nt*128 + cl; addr = (t*BH + b_*HH)*4 + n
    const int b_ = my >> 4;
    const int t0 = (my & 15) << 7;
    float* plane = g_pre + ((size_t)t0 * BH + (size_t)b_ * HH) * 4 + nt * 128;
    const size_t rstride = (size_t)BH * 4;

    #pragma unroll
    for (int mi = 0; mi < 4; mi++) {
        const int r0 = wm * 64 + mi * 16 + (lane >> 2);
        #pragma unroll
        for (int ni = 0; ni < 4; ni++) {
            const int cl = wn * 32 + ni * 8 + (lane & 3) * 2;
            float* p0 = plane + (size_t)r0 * rstride + cl;
            float* p1 = p0 + 8 * rstride;
            *(float2*)p0 = make_float2(acc[mi][ni][0], acc[mi][ni][1]);
            *(float2*)p1 = make_float2(acc[mi][ni][2], acc[mi][ni][3]);
        }
    }
}

// ---------------------------------------------------------------------------
// Scan: one thread per (b,h). Gate-interleaved pre -> one float4 per step.
// HW tanh.approx activations; SDEPTH=16 ping-pong gives ~900-cycle prefetch
// lead so DRAM latency is fully covered by the serial compute.
// ---------------------------------------------------------------------------
__device__ __forceinline__ float ftanh(float x) {
    float y;
    asm("tanh.approx.f32 %0, %1;" : "=f"(y) : "f"(x));
    return y;
}
__device__ __forceinline__ float sigf(float x) {
    return __fmaf_rn(0.5f, ftanh(0.5f * x), 0.5f);
}

__device__ __forceinline__ void ldg_v4(float4& v, const float* p) {
    asm volatile("ld.global.cg.v4.f32 {%0,%1,%2,%3}, [%4];"
                 : "=f"(v.x), "=f"(v.y), "=f"(v.z), "=f"(v.w) : "l"(p));
}

#define SCAN_THREADS 64
#define SDEPTH 16

__global__ __launch_bounds__(SCAN_THREADS, 1) void scan_kernel(
    const float* __restrict__ u_f, const float* __restrict__ b_f,
    const float* __restrict__ u_i, const float* __restrict__ b_i,
    const float* __restrict__ u_o, const float* __restrict__ b_o,
    const float* __restrict__ u_c, const float* __restrict__ b_c,
    float* __restrict__ out)
{
    const int idx = blockIdx.x * SCAN_THREADS + threadIdx.x;   // 0..BH-1
    const int b = idx >> 9;
    const int h = idx & 511;

    const float uf = u_f[h], bf = b_f[h];
    const float ui = u_i[h], bi = b_i[h];
    const float uo = u_o[h], bo = b_o[h];
    const float uc = u_c[h], bc = b_c[h];

    const float* __restrict__ pp = g_pre + (size_t)idx * 4;    // step stride BH*4
    const size_t tstride = (size_t)BH * 4;
    float* __restrict__ ho = out + (size_t)b * TT * HH + h;

    float4 bufA[SDEPTH], bufB[SDEPTH];
    #pragma unroll
    for (int j = 0; j < SDEPTH; j++) ldg_v4(bufA[j], pp + (size_t)j * tstride);

    float hv = 0.0f, cv = 0.0f;

    #pragma unroll 1
    for (int tb = 0; tb < TT; tb += 2 * SDEPTH) {
        // phase 1: prefetch next SDEPTH into bufB, compute on bufA
        #pragma unroll
        for (int j = 0; j < SDEPTH; j++)
            ldg_v4(bufB[j], pp + (size_t)(tb + SDEPTH + j) * tstride);
        #pragma unroll
        for (int j = 0; j < SDEPTH; j++) {
            const float gf = bufA[j].x + fmaf(hv, uf, bf);
            const float gi = bufA[j].y + fmaf(hv, ui, bi);
            const float go = bufA[j].z + fmaf(hv, uo, bo);
            const float gc = bufA[j].w + fmaf(hv, uc, bc);
            cv = fmaf(sigf(gf), cv, sigf(gi) * ftanh(gc));
            hv = sigf(go) * ftanh(cv);
            ho[(size_t)(tb + j) * HH] = hv;
        }
        // phase 2: prefetch following SDEPTH into bufA (guarded), compute bufB
        if (tb + 2 * SDEPTH < TT) {
            #pragma unroll
            for (int j = 0; j < SDEPTH; j++)
                ldg_v4(bufA[j], pp + (size_t)(tb + 2 * SDEPTH + j) * tstride);
        }
        #pragma unroll
        for (int j = 0; j < SDEPTH; j++) {
            const float gf = bufB[j].x + fmaf(hv, uf, bf);
            const float gi = bufB[j].y + fmaf(hv, ui, bi);
            const float go = bufB[j].z + fmaf(hv, uo, bo);
            const float gc = bufB[j].w + fmaf(hv, uc, bc);
            cv = fmaf(sigf(gf), cv, sigf(gi) * ftanh(gc));
            hv = sigf(go) * ftanh(cv);
            ho[(size_t)(tb + SDEPTH + j) * HH] = hv;
        }
    }

    // h_t / c_t tails are zeros
    out[(size_t)BB * TT * HH + idx]      = 0.0f;
    out[(size_t)BB * TT * HH + BH + idx] = 0.0f;
}

// ---------------------------------------------------------------------------
// Launch
// ---------------------------------------------------------------------------
extern "C" void kernel_launch(void* const* d_in, const int* in_sizes, int n_in,
                              void* d_out, int out_size)
{
    const float* x   = (const float*)d_in[0];
    const float* W_f = (const float*)d_in[1];
    const float* u_f = (const float*)d_in[2];
    const float* b_f = (const float*)d_in[3];
    const float* W_i = (const float*)d_in[4];
    const float* u_i = (const float*)d_in[5];
    const float* b_i = (const float*)d_in[6];
    const float* W_o = (const float*)d_in[7];
    const float* u_o = (const float*)d_in[8];
    const float* b_o = (const float*)d_in[9];
    const float* W_c = (const float*)d_in[10];
    const float* u_c = (const float*)d_in[11];
    const float* b_c = (const float*)d_in[12];
    float* out = (float*)d_out;

    static int smem_set = 0;
    if (!smem_set) {
        cudaFuncSetAttribute(gemm_mma_kernel,
                             cudaFuncAttributeMaxDynamicSharedMemorySize,
                             2 * STAGE_B);
        smem_set = 1;
    }

    convert_x_kernel<<<(int)((size_t)MM * II / (256 * 4)), 256>>>(x);
    convert_w_kernel<<<4 * II * HH / 256, 256>>>(W_f, W_i, W_o, W_c);

    dim3 ggrid(16, 512);
    gemm_mma_kernel<<<ggrid, 256, 2 * STAGE_B>>>();

    scan_kernel<<<BH / SCAN_THREADS, SCAN_THREADS>>>(u_f, b_f, u_i, b_i,
                                                     u_o, b_o, u_c, b_c, out);
}